// round 16
// baseline (speedup 1.0000x reference)
#include <cuda_runtime.h>
#include <cuda_fp16.h>
#include <cstdint>
#include <math.h>

#define B_  64
#define S_  2048
#define U_  1024
#define M_  (B_ * S_)   // 131072

// ---------------- scratch (device globals; no allocs allowed) ---------------
__device__ float g_Ws[B_ * U_];                     // s_prev @ W_w + W_b
__device__ float g_scores[M_];                      // pre-softmax scores
__device__ __half g_Ah[(size_t)M_ * U_];            // HS as fp16 (256 MB)
__device__ __half g_Bh[U_ * U_];                    // Uw^T fp16 [n][k]

// ---------------- K0: prep (init + transpose Uw) -----------------------------
__global__ void __launch_bounds__(256) k_prep(const float* __restrict__ Uw,
                                              const float* __restrict__ Wb,
                                              const float* __restrict__ Vb,
                                              float* __restrict__ ctx_out) {
    int i = blockIdx.x * 256 + threadIdx.x;     // 0 .. 1M-1
    int k = i >> 10, n = i & (U_ - 1);
    g_Bh[n * U_ + k] = __float2half_rn(Uw[k * U_ + n]);
    if (i < B_ * U_) { g_Ws[i] = Wb[i & (U_ - 1)]; ctx_out[i] = 0.0f; }
    if (i < M_) g_scores[i] = Vb[0];
}

// ---------------- K1: HS -> fp16 ---------------------------------------------
__global__ void __launch_bounds__(256) k_cvtA(const float* __restrict__ HS) {
    size_t i = (size_t)blockIdx.x * 256 + threadIdx.x;
    size_t stride = (size_t)gridDim.x * 256;
    size_t n4 = (size_t)M_ * U_ / 4;
    for (; i < n4; i += stride) {
        float4 v = ((const float4*)HS)[i];
        ((__half2*)g_Ah)[i * 2]     = __floats2half2_rn(v.x, v.y);
        ((__half2*)g_Ah)[i * 2 + 1] = __floats2half2_rn(v.z, v.w);
    }
}

// ---------------- K2: Ws += s_prev @ W_w ------------------------------------
__global__ void __launch_bounds__(128) k_ws(const float* __restrict__ s_prev,
                                            const float* __restrict__ Ww) {
    __shared__ float s_sm[B_][128];
    const int tid = threadIdx.x;
    const int u   = blockIdx.x * 128 + tid;
    const int k0  = blockIdx.y * 128;
    for (int j = 0; j < 64; j++) {
        int idx = tid + 128 * j;
        s_sm[idx >> 7][idx & 127] = s_prev[(idx >> 7) * U_ + k0 + (idx & 127)];
    }
    __syncthreads();
    float acc[B_];
    #pragma unroll
    for (int b = 0; b < B_; b++) acc[b] = 0.0f;
    for (int kk = 0; kk < 128; kk++) {
        float w = Ww[(k0 + kk) * U_ + u];
        #pragma unroll
        for (int b = 0; b < B_; b++) acc[b] += s_sm[b][kk] * w;
    }
    #pragma unroll
    for (int b = 0; b < B_; b++) atomicAdd(&g_Ws[b * U_ + u], acc[b]);
}

// ---------------- mma.sync helpers -------------------------------------------
__device__ __forceinline__ uint32_t smem_u32(const void* p) {
    uint32_t a;
    asm("{ .reg .u64 t; cvta.to.shared.u64 t, %1; cvt.u32.u64 %0, t; }"
        : "=r"(a) : "l"(p));
    return a;
}
__device__ __forceinline__ void cp16(uint32_t saddr, const void* g) {
    asm volatile("cp.async.cg.shared.global [%0], [%1], 16;"
                 :: "r"(saddr), "l"(g) : "memory");
}
#define CP_COMMIT() asm volatile("cp.async.commit_group;" ::: "memory")
#define CP_WAIT(N)  asm volatile("cp.async.wait_group %0;" :: "n"(N) : "memory")

__device__ __forceinline__ void mma_f16(float* c, const uint32_t* a,
                                        uint32_t b0, uint32_t b1) {
    asm volatile(
        "mma.sync.aligned.m16n8k16.row.col.f32.f16.f16.f32 "
        "{%0,%1,%2,%3}, {%4,%5,%6,%7}, {%8,%9}, {%0,%1,%2,%3};"
        : "+f"(c[0]), "+f"(c[1]), "+f"(c[2]), "+f"(c[3])
        : "r"(a[0]), "r"(a[1]), "r"(a[2]), "r"(a[3]), "r"(b0), "r"(b1));
}
__device__ __forceinline__ void ldsm_x4(uint32_t& r0, uint32_t& r1,
                                        uint32_t& r2, uint32_t& r3, uint32_t a) {
    asm volatile("ldmatrix.sync.aligned.m8n8.x4.shared.b16 {%0,%1,%2,%3}, [%4];"
                 : "=r"(r0), "=r"(r1), "=r"(r2), "=r"(r3) : "r"(a));
}

// ---------------- K3: scores GEMM (fp16, 1 CTA/SM, frag double-buffer) -------
// C tile BM=128 x BN=128, BK=64; 8 warps (2m x 4n), warp tile 64x32.
// 4-stage cp.async ring + 2-deep fragment pipeline inside each chunk.
#define BMm 128
#define BNm 128
#define BKm 64
#define RSH 72                      // fp16 row stride (144 B), pad 8
#define A_TILE (BMm * RSH * 2)      // 18432 B
#define B_TILE (BNm * RSH * 2)      // 18432 B
#define STG_SZ (A_TILE + B_TILE)    // 36864 B
#define OFF_B   A_TILE
#define NSTG 4
#define SMEM_K3 (NSTG * STG_SZ)     // 147456 B
#define NCHm (U_ / BKm)             // 16 k-chunks

__global__ void __launch_bounds__(256) k_scores_mma(const float* __restrict__ Ub,
                                                    const float* __restrict__ Vw) {
    extern __shared__ char sm[];
    __shared__ float sWs[BNm], sUb[BNm], sVw[BNm];

    const int tid  = threadIdx.x;
    const int wid  = tid >> 5;
    const int lane = tid & 31;
    const int gid  = lane >> 2;
    const int tig  = lane & 3;
    const int warp_m = wid & 1;                    // 0..1, 64 rows each
    const int warp_n = wid >> 1;                   // 0..3, 32 cols each

    const int col0 = blockIdx.x * BNm;
    const int row0 = blockIdx.y * BMm;
    const int b    = row0 >> 11;                   // batch (S=2048)

    if (tid < BNm) {
        sWs[tid] = g_Ws[b * U_ + col0 + tid];
        sUb[tid] = Ub[col0 + tid];
        sVw[tid] = Vw[col0 + tid];
    }

    const __half* gA = g_Ah + (size_t)row0 * U_;
    const __half* gB = g_Bh + (size_t)col0 * U_;

    const uint32_t sb = smem_u32(sm);

    const int lm_m = lane >> 3, lm_r = lane & 7;
    // B (stored [n][k]): matrices -> {n+0,k+0},{n+0,k+8},{n+8,k+0},{n+8,k+8}
    const uint32_t lmB_off =
        (uint32_t)(((warp_n * 32) + ((lm_m & 2) ? 8 : 0) + lm_r) * RSH
                   + ((lm_m & 1) ? 8 : 0)) * 2;
    // A (stored [m][k]): matrices -> {m+0,k+0},{m+8,k+0},{m+0,k+8},{m+8,k+8}
    const uint32_t lmA_off =
        (uint32_t)(((warp_m * 64) + ((lm_m & 1) ? 8 : 0) + lm_r) * RSH
                   + ((lm_m & 2) ? 8 : 0)) * 2;

    // chunk kc -> stage kc%4 : A 1024 cp16 (4/thread); B 1024 cp16 (4/thread)
    auto issue = [&](int kc) {
        if (kc < NCHm) {
            const int kofs = kc * BKm;
            const uint32_t stb = sb + (kc % NSTG) * STG_SZ;
            #pragma unroll
            for (int i = 0; i < 4; i++) {
                int c = tid + i * 256;             // 0..1023
                int r = c >> 3, q = (c & 7) * 8;   // row, fp16 offset
                uint32_t so = (uint32_t)(r * RSH + q) * 2;
                cp16(stb + so, gA + (size_t)r * U_ + kofs + q);
                cp16(stb + OFF_B + so, gB + (size_t)r * U_ + kofs + q);
            }
        }
        CP_COMMIT();
    };

    float acc[4][4][4];
    #pragma unroll
    for (int mt = 0; mt < 4; mt++)
        #pragma unroll
        for (int nt = 0; nt < 4; nt++)
            #pragma unroll
            for (int j = 0; j < 4; j++) acc[mt][nt][j] = 0.0f;

    issue(0);
    issue(1);
    issue(2);

    // fragment double-buffer: Af[2][4 mt][4], Bf[2][2 ntp][4]
    uint32_t Af[2][4][4], Bf[2][2][4];

    for (int kc = 0; kc < NCHm; kc++) {
        // groups issued: 0..kc+2 ; <=2 pending => group kc complete
        CP_WAIT(2);
        __syncthreads();
        // issue(kc+3) writes stage (kc+3)%4 == (kc-1)%4 — consumed last
        // iteration, all readers passed the barrier above. Safe.
        issue(kc + 3);

        const uint32_t stg = sb + (kc % NSTG) * STG_SZ;
        const uint32_t a_base = stg + lmA_off;
        const uint32_t b_base = stg + OFF_B + lmB_off;

        // load slab 0 fragments into buffer 0
        #pragma unroll
        for (int mt = 0; mt < 4; mt++) {
            uint32_t t = (uint32_t)(mt * 16 * RSH) * 2;
            ldsm_x4(Af[0][mt][0], Af[0][mt][1], Af[0][mt][2], Af[0][mt][3],
                    a_base + t);
        }
        #pragma unroll
        for (int ntp = 0; ntp < 2; ntp++) {
            uint32_t t = (uint32_t)(ntp * 16 * RSH) * 2;
            ldsm_x4(Bf[0][ntp][0], Bf[0][ntp][1], Bf[0][ntp][2], Bf[0][ntp][3],
                    b_base + t);
        }

        #pragma unroll
        for (int slab = 0; slab < 4; slab++) {
            const int cur = slab & 1;
            const int nxt = cur ^ 1;
            // prefetch next slab's fragments BEFORE current MMAs (independent)
            if (slab < 3) {
                const uint32_t kb = (uint32_t)((slab + 1) * 16) * 2;
                #pragma unroll
                for (int mt = 0; mt < 4; mt++) {
                    uint32_t t = (uint32_t)(mt * 16 * RSH) * 2 + kb;
                    ldsm_x4(Af[nxt][mt][0], Af[nxt][mt][1],
                            Af[nxt][mt][2], Af[nxt][mt][3], a_base + t);
                }
                #pragma unroll
                for (int ntp = 0; ntp < 2; ntp++) {
                    uint32_t t = (uint32_t)(ntp * 16 * RSH) * 2 + kb;
                    ldsm_x4(Bf[nxt][ntp][0], Bf[nxt][ntp][1],
                            Bf[nxt][ntp][2], Bf[nxt][ntp][3], b_base + t);
                }
            }
            #pragma unroll
            for (int ntp = 0; ntp < 2; ntp++)
                #pragma unroll
                for (int mt = 0; mt < 4; mt++) {
                    mma_f16(acc[mt][2 * ntp],     Af[cur][mt],
                            Bf[cur][ntp][0], Bf[cur][ntp][1]);
                    mma_f16(acc[mt][2 * ntp + 1], Af[cur][mt],
                            Bf[cur][ntp][2], Bf[cur][ntp][3]);
                }
        }
    }

    // epilogue: tanh + dot with Vw, reduce over n within thread, then over tig
    #pragma unroll
    for (int mt = 0; mt < 4; mt++) {
        float pl = 0.0f, ph = 0.0f;
        #pragma unroll
        for (int nt = 0; nt < 4; nt++) {
            int nb = warp_n * 32 + nt * 8 + 2 * tig;
            pl += tanhf(acc[mt][nt][0] + sWs[nb]     + sUb[nb])     * sVw[nb];
            pl += tanhf(acc[mt][nt][1] + sWs[nb + 1] + sUb[nb + 1]) * sVw[nb + 1];
            ph += tanhf(acc[mt][nt][2] + sWs[nb]     + sUb[nb])     * sVw[nb];
            ph += tanhf(acc[mt][nt][3] + sWs[nb + 1] + sUb[nb + 1]) * sVw[nb + 1];
        }
        pl += __shfl_xor_sync(0xffffffffu, pl, 1);
        pl += __shfl_xor_sync(0xffffffffu, pl, 2);
        ph += __shfl_xor_sync(0xffffffffu, ph, 1);
        ph += __shfl_xor_sync(0xffffffffu, ph, 2);
        if (tig == 0) {
            int r = row0 + warp_m * 64 + mt * 16 + gid;
            atomicAdd(&g_scores[r], pl);
            atomicAdd(&g_scores[r + 8], ph);
        }
    }
}

// ---------------- K4: softmax over S per batch -------------------------------
__global__ void __launch_bounds__(256) k_softmax(float* __restrict__ w_out) {
    __shared__ float red[256];
    const int b   = blockIdx.x;
    const int tid = threadIdx.x;
    const float* sc = g_scores + b * S_;
    float* w = w_out + b * S_;

    float m = -1e30f;
    for (int s = tid; s < S_; s += 256) m = fmaxf(m, sc[s]);
    red[tid] = m; __syncthreads();
    for (int o = 128; o > 0; o >>= 1) {
        if (tid < o) red[tid] = fmaxf(red[tid], red[tid + o]);
        __syncthreads();
    }
    m = red[0];
    __syncthreads();

    float sum = 0.0f;
    for (int s = tid; s < S_; s += 256) {
        float e = expf(sc[s] - m);
        w[s] = e;
        sum += e;
    }
    red[tid] = sum; __syncthreads();
    for (int o = 128; o > 0; o >>= 1) {
        if (tid < o) red[tid] += red[tid + o];
        __syncthreads();
    }
    float inv = 1.0f / red[0];
    for (int s = tid; s < S_; s += 256) w[s] *= inv;
}

// ---------------- K5: context = sum_s w * HS ---------------------------------
__global__ void __launch_bounds__(256) k_context(const float* __restrict__ HS,
                                                 const float* __restrict__ w_in,
                                                 float* __restrict__ ctx) {
    __shared__ float w_sm[256];
    const int tid = threadIdx.x;
    const int b   = blockIdx.y;
    const int s0  = blockIdx.x * 256;

    w_sm[tid] = w_in[b * S_ + s0 + tid];
    __syncthreads();

    const int u = tid * 4;
    float ax = 0.f, ay = 0.f, az = 0.f, aw = 0.f;
    const float* base = HS + ((size_t)b * S_ + s0) * U_ + u;
    for (int s = 0; s < 256; s++) {
        float wv = w_sm[s];
        float4 h = *(const float4*)(base + (size_t)s * U_);
        ax += wv * h.x; ay += wv * h.y; az += wv * h.z; aw += wv * h.w;
    }
    atomicAdd(&ctx[b * U_ + u + 0], ax);
    atomicAdd(&ctx[b * U_ + u + 1], ay);
    atomicAdd(&ctx[b * U_ + u + 2], az);
    atomicAdd(&ctx[b * U_ + u + 3], aw);
}

// ---------------- launch -----------------------------------------------------
extern "C" void kernel_launch(void* const* d_in, const int* in_sizes, int n_in,
                              void* d_out, int out_size) {
    const float* s_prev = (const float*)d_in[0];
    const float* HS     = (const float*)d_in[1];
    const float* Ww     = (const float*)d_in[2];
    const float* Wb     = (const float*)d_in[3];
    const float* Uw     = (const float*)d_in[4];
    const float* Ub     = (const float*)d_in[5];
    const float* Vw     = (const float*)d_in[6];
    const float* Vb     = (const float*)d_in[7];

    float* ctx     = (float*)d_out;            // [64, 1024]
    float* weights = (float*)d_out + B_ * U_;  // [64, 2048, 1]

    cudaFuncSetAttribute(k_scores_mma,
                         cudaFuncAttributeMaxDynamicSharedMemorySize, SMEM_K3);

    // launch order keeps the GEMM as launch #4 for the profiler
    k_prep<<<U_ * U_ / 256, 256>>>(Uw, Wb, Vb, ctx);
    k_cvtA<<<8192, 256>>>(HS);
    k_ws<<<dim3(8, 8), 128>>>(s_prev, Ww);
    k_scores_mma<<<dim3(U_ / BNm, M_ / BMm), 256, SMEM_K3>>>(Ub, Vw);
    k_softmax<<<B_, 256>>>(weights);
    k_context<<<dim3(S_ / 256, B_), 256>>>(HS, weights, ctx);
}

// round 17
// speedup vs baseline: 1.1276x; 1.1276x over previous
#include <cuda_runtime.h>
#include <cuda_fp16.h>
#include <cstdint>
#include <math.h>

#define B_  64
#define S_  2048
#define U_  1024
#define M_  (B_ * S_)   // 131072

// ---------------- scratch (device globals; no allocs allowed) ---------------
__device__ float g_Ws[B_ * U_];                     // s_prev @ W_w + W_b
__device__ float g_scores[M_];                      // pre-softmax scores
__device__ __half g_Ah[(size_t)M_ * U_];            // HS as fp16 (256 MB)
__device__ __half g_Bh[U_ * U_];                    // Uw^T fp16 [n][k]

// ---------------- K0: prep (init + transpose Uw) -----------------------------
__global__ void __launch_bounds__(256) k_prep(const float* __restrict__ Uw,
                                              const float* __restrict__ Wb,
                                              const float* __restrict__ Vb,
                                              float* __restrict__ ctx_out) {
    int i = blockIdx.x * 256 + threadIdx.x;     // 0 .. 1M-1
    int k = i >> 10, n = i & (U_ - 1);
    g_Bh[n * U_ + k] = __float2half_rn(Uw[k * U_ + n]);
    if (i < B_ * U_) { g_Ws[i] = Wb[i & (U_ - 1)]; ctx_out[i] = 0.0f; }
    if (i < M_) g_scores[i] = Vb[0];
}

// ---------------- K1: HS -> fp16 ---------------------------------------------
__global__ void __launch_bounds__(256) k_cvtA(const float* __restrict__ HS) {
    size_t i = (size_t)blockIdx.x * 256 + threadIdx.x;
    size_t stride = (size_t)gridDim.x * 256;
    size_t n4 = (size_t)M_ * U_ / 4;
    for (; i < n4; i += stride) {
        float4 v = ((const float4*)HS)[i];
        ((__half2*)g_Ah)[i * 2]     = __floats2half2_rn(v.x, v.y);
        ((__half2*)g_Ah)[i * 2 + 1] = __floats2half2_rn(v.z, v.w);
    }
}

// ---------------- K2: Ws += s_prev @ W_w ------------------------------------
__global__ void __launch_bounds__(128) k_ws(const float* __restrict__ s_prev,
                                            const float* __restrict__ Ww) {
    __shared__ float s_sm[B_][128];
    const int tid = threadIdx.x;
    const int u   = blockIdx.x * 128 + tid;
    const int k0  = blockIdx.y * 128;
    for (int j = 0; j < 64; j++) {
        int idx = tid + 128 * j;
        s_sm[idx >> 7][idx & 127] = s_prev[(idx >> 7) * U_ + k0 + (idx & 127)];
    }
    __syncthreads();
    float acc[B_];
    #pragma unroll
    for (int b = 0; b < B_; b++) acc[b] = 0.0f;
    for (int kk = 0; kk < 128; kk++) {
        float w = Ww[(k0 + kk) * U_ + u];
        #pragma unroll
        for (int b = 0; b < B_; b++) acc[b] += s_sm[b][kk] * w;
    }
    #pragma unroll
    for (int b = 0; b < B_; b++) atomicAdd(&g_Ws[b * U_ + u], acc[b]);
}

// ---------------- mma.sync helpers -------------------------------------------
__device__ __forceinline__ uint32_t smem_u32(const void* p) {
    uint32_t a;
    asm("{ .reg .u64 t; cvta.to.shared.u64 t, %1; cvt.u32.u64 %0, t; }"
        : "=r"(a) : "l"(p));
    return a;
}
__device__ __forceinline__ void cp16(uint32_t saddr, const void* g) {
    asm volatile("cp.async.cg.shared.global [%0], [%1], 16;"
                 :: "r"(saddr), "l"(g) : "memory");
}
#define CP_COMMIT() asm volatile("cp.async.commit_group;" ::: "memory")
#define CP_WAIT(N)  asm volatile("cp.async.wait_group %0;" :: "n"(N) : "memory")

__device__ __forceinline__ void mma_f16(float* c, const uint32_t* a,
                                        uint32_t b0, uint32_t b1) {
    asm volatile(
        "mma.sync.aligned.m16n8k16.row.col.f32.f16.f16.f32 "
        "{%0,%1,%2,%3}, {%4,%5,%6,%7}, {%8,%9}, {%0,%1,%2,%3};"
        : "+f"(c[0]), "+f"(c[1]), "+f"(c[2]), "+f"(c[3])
        : "r"(a[0]), "r"(a[1]), "r"(a[2]), "r"(a[3]), "r"(b0), "r"(b1));
}
__device__ __forceinline__ void ldsm_x4(uint32_t& r0, uint32_t& r1,
                                        uint32_t& r2, uint32_t& r3, uint32_t a) {
    asm volatile("ldmatrix.sync.aligned.m8n8.x4.shared.b16 {%0,%1,%2,%3}, [%4];"
                 : "=r"(r0), "=r"(r1), "=r"(r2), "=r"(r3) : "r"(a));
}

// ---------------- K3: scores GEMM (fp16, BM128 x BN256, warp 64x64) ----------
// 8 warps (2m x 4n), warp tile 64x64, BK=64; 3-stage ring, 1 barrier/chunk.
#define BMm 128
#define BNm 256
#define BKm 64
#define RSH 72                      // fp16 row stride (144 B), pad 8
#define A_TILE (BMm * RSH * 2)      // 18432 B
#define B_TILE (BNm * RSH * 2)      // 36864 B
#define STG_SZ (A_TILE + B_TILE)    // 55296 B
#define OFF_B   A_TILE
#define NSTG 3
#define SMEM_K3 (NSTG * STG_SZ)     // 165888 B
#define NCHm (U_ / BKm)             // 16 k-chunks

__global__ void __launch_bounds__(256) k_scores_mma(const float* __restrict__ Ub,
                                                    const float* __restrict__ Vw) {
    extern __shared__ char sm[];
    __shared__ float sWs[BNm], sUb[BNm], sVw[BNm];

    const int tid  = threadIdx.x;
    const int wid  = tid >> 5;
    const int lane = tid & 31;
    const int gid  = lane >> 2;
    const int tig  = lane & 3;
    const int warp_m = wid & 1;                    // 0..1, 64 rows each
    const int warp_n = wid >> 1;                   // 0..3, 64 cols each

    const int col0 = blockIdx.x * BNm;
    const int row0 = blockIdx.y * BMm;
    const int b    = row0 >> 11;                   // batch (S=2048)

    if (tid < BNm) {
        sWs[tid] = g_Ws[b * U_ + col0 + tid];
        sUb[tid] = Ub[col0 + tid];
        sVw[tid] = Vw[col0 + tid];
    }

    const __half* gA = g_Ah + (size_t)row0 * U_;
    const __half* gB = g_Bh + (size_t)col0 * U_;

    const uint32_t sb = smem_u32(sm);

    const int lm_m = lane >> 3, lm_r = lane & 7;
    // B (stored [n][k]): matrices -> {n+0,k+0},{n+0,k+8},{n+8,k+0},{n+8,k+8}
    const uint32_t lmB_off =
        (uint32_t)(((warp_n * 64) + ((lm_m & 2) ? 8 : 0) + lm_r) * RSH
                   + ((lm_m & 1) ? 8 : 0)) * 2;
    // A (stored [m][k]): matrices -> {m+0,k+0},{m+8,k+0},{m+0,k+8},{m+8,k+8}
    const uint32_t lmA_off =
        (uint32_t)(((warp_m * 64) + ((lm_m & 1) ? 8 : 0) + lm_r) * RSH
                   + ((lm_m & 2) ? 8 : 0)) * 2;

    // chunk kc -> stage kc%3 : A 1024 cp16 (4/thr); B 2048 cp16 (8/thr)
    auto issue = [&](int kc) {
        if (kc < NCHm) {
            const int kofs = kc * BKm;
            const uint32_t stb = sb + (kc % NSTG) * STG_SZ;
            #pragma unroll
            for (int i = 0; i < 4; i++) {
                int c = tid + i * 256;             // 0..1023
                int r = c >> 3, q = (c & 7) * 8;
                cp16(stb + (uint32_t)(r * RSH + q) * 2,
                     gA + (size_t)r * U_ + kofs + q);
            }
            #pragma unroll
            for (int i = 0; i < 8; i++) {
                int c = tid + i * 256;             // 0..2047
                int r = c >> 3, q = (c & 7) * 8;
                cp16(stb + OFF_B + (uint32_t)(r * RSH + q) * 2,
                     gB + (size_t)r * U_ + kofs + q);
            }
        }
        CP_COMMIT();
    };

    float acc[4][8][4];
    #pragma unroll
    for (int mt = 0; mt < 4; mt++)
        #pragma unroll
        for (int nt = 0; nt < 8; nt++)
            #pragma unroll
            for (int j = 0; j < 4; j++) acc[mt][nt][j] = 0.0f;

    issue(0);
    issue(1);

    for (int kc = 0; kc < NCHm; kc++) {
        // groups issued: 0..kc+1 ; <=1 pending => group kc complete
        CP_WAIT(1);
        __syncthreads();
        // issue(kc+2) writes stage (kc+2)%3 == (kc-1)%3 — all readers passed
        // the barrier above; in-flight groups never touch stage kc%3.
        issue(kc + 2);

        const uint32_t stg = sb + (kc % NSTG) * STG_SZ;
        const uint32_t a_base = stg + lmA_off;
        const uint32_t b_base = stg + OFF_B + lmB_off;

        #pragma unroll
        for (int slab = 0; slab < 4; slab++) {
            const uint32_t kb = (uint32_t)(slab * 16) * 2;
            uint32_t Ah[4][4];
            #pragma unroll
            for (int mt = 0; mt < 4; mt++) {
                uint32_t t = (uint32_t)(mt * 16 * RSH) * 2 + kb;
                ldsm_x4(Ah[mt][0], Ah[mt][1], Ah[mt][2], Ah[mt][3], a_base + t);
            }
            #pragma unroll
            for (int ntp = 0; ntp < 4; ntp++) {
                uint32_t b0, b1, b2, b3;
                uint32_t t = (uint32_t)(ntp * 16 * RSH) * 2 + kb;
                ldsm_x4(b0, b1, b2, b3, b_base + t);
                #pragma unroll
                for (int mt = 0; mt < 4; mt++) {
                    mma_f16(acc[mt][2 * ntp],     Ah[mt], b0, b1);
                    mma_f16(acc[mt][2 * ntp + 1], Ah[mt], b2, b3);
                }
            }
        }
    }

    // epilogue: tanh + dot with Vw, reduce over n within thread, then over tig
    #pragma unroll
    for (int mt = 0; mt < 4; mt++) {
        float pl = 0.0f, ph = 0.0f;
        #pragma unroll
        for (int nt = 0; nt < 8; nt++) {
            int nb = warp_n * 64 + nt * 8 + 2 * tig;
            pl += tanhf(acc[mt][nt][0] + sWs[nb]     + sUb[nb])     * sVw[nb];
            pl += tanhf(acc[mt][nt][1] + sWs[nb + 1] + sUb[nb + 1]) * sVw[nb + 1];
            ph += tanhf(acc[mt][nt][2] + sWs[nb]     + sUb[nb])     * sVw[nb];
            ph += tanhf(acc[mt][nt][3] + sWs[nb + 1] + sUb[nb + 1]) * sVw[nb + 1];
        }
        pl += __shfl_xor_sync(0xffffffffu, pl, 1);
        pl += __shfl_xor_sync(0xffffffffu, pl, 2);
        ph += __shfl_xor_sync(0xffffffffu, ph, 1);
        ph += __shfl_xor_sync(0xffffffffu, ph, 2);
        if (tig == 0) {
            int r = row0 + warp_m * 64 + mt * 16 + gid;
            atomicAdd(&g_scores[r], pl);
            atomicAdd(&g_scores[r + 8], ph);
        }
    }
}

// ---------------- K4: softmax over S per batch -------------------------------
__global__ void __launch_bounds__(256) k_softmax(float* __restrict__ w_out) {
    __shared__ float red[256];
    const int b   = blockIdx.x;
    const int tid = threadIdx.x;
    const float* sc = g_scores + b * S_;
    float* w = w_out + b * S_;

    float m = -1e30f;
    for (int s = tid; s < S_; s += 256) m = fmaxf(m, sc[s]);
    red[tid] = m; __syncthreads();
    for (int o = 128; o > 0; o >>= 1) {
        if (tid < o) red[tid] = fmaxf(red[tid], red[tid + o]);
        __syncthreads();
    }
    m = red[0];
    __syncthreads();

    float sum = 0.0f;
    for (int s = tid; s < S_; s += 256) {
        float e = expf(sc[s] - m);
        w[s] = e;
        sum += e;
    }
    red[tid] = sum; __syncthreads();
    for (int o = 128; o > 0; o >>= 1) {
        if (tid < o) red[tid] += red[tid + o];
        __syncthreads();
    }
    float inv = 1.0f / red[0];
    for (int s = tid; s < S_; s += 256) w[s] *= inv;
}

// ---------------- K5: context = sum_s w * HS(fp16) ---------------------------
__global__ void __launch_bounds__(256) k_context(const float* __restrict__ w_in,
                                                 float* __restrict__ ctx) {
    __shared__ float w_sm[256];
    const int tid = threadIdx.x;
    const int b   = blockIdx.y;
    const int s0  = blockIdx.x * 256;

    w_sm[tid] = w_in[b * S_ + s0 + tid];
    __syncthreads();

    const int u = tid * 4;
    float ax = 0.f, ay = 0.f, az = 0.f, aw = 0.f;
    const __half* base = g_Ah + ((size_t)b * S_ + s0) * U_ + u;
    for (int s = 0; s < 256; s++) {
        float wv = w_sm[s];
        uint2 raw = *(const uint2*)(base + (size_t)s * U_);
        __half2 h0 = *(__half2*)&raw.x;
        __half2 h1 = *(__half2*)&raw.y;
        float2 f0 = __half22float2(h0);
        float2 f1 = __half22float2(h1);
        ax += wv * f0.x; ay += wv * f0.y; az += wv * f1.x; aw += wv * f1.y;
    }
    atomicAdd(&ctx[b * U_ + u + 0], ax);
    atomicAdd(&ctx[b * U_ + u + 1], ay);
    atomicAdd(&ctx[b * U_ + u + 2], az);
    atomicAdd(&ctx[b * U_ + u + 3], aw);
}

// ---------------- launch -----------------------------------------------------
extern "C" void kernel_launch(void* const* d_in, const int* in_sizes, int n_in,
                              void* d_out, int out_size) {
    const float* s_prev = (const float*)d_in[0];
    const float* HS     = (const float*)d_in[1];
    const float* Ww     = (const float*)d_in[2];
    const float* Wb     = (const float*)d_in[3];
    const float* Uw     = (const float*)d_in[4];
    const float* Ub     = (const float*)d_in[5];
    const float* Vw     = (const float*)d_in[6];
    const float* Vb     = (const float*)d_in[7];

    float* ctx     = (float*)d_out;            // [64, 1024]
    float* weights = (float*)d_out + B_ * U_;  // [64, 2048, 1]

    cudaFuncSetAttribute(k_scores_mma,
                         cudaFuncAttributeMaxDynamicSharedMemorySize, SMEM_K3);

    // launch order keeps the GEMM as launch #4 for the profiler
    k_prep<<<U_ * U_ / 256, 256>>>(Uw, Wb, Vb, ctx);
    k_cvtA<<<8192, 256>>>(HS);
    k_ws<<<dim3(8, 8), 128>>>(s_prev, Ww);
    k_scores_mma<<<dim3(U_ / BNm, M_ / BMm), 256, SMEM_K3>>>(Ub, Vw);
    k_softmax<<<B_, 256>>>(weights);
    k_context<<<dim3(S_ / 256, B_), 256>>>(weights, ctx);
}